// round 1
// baseline (speedup 1.0000x reference)
#include <cuda_runtime.h>
#include <math.h>

#define N_NODES 50000
#define F 128
#define F4 (F/4)          // 32 float4 per row
#define EMAX 600000

// ---------------- scratch (no allocations allowed) ----------------
__device__ float g_h[N_NODES * F];     // GEMM output (gather table)
__device__ float g_a[N_NODES * F];     // aggregated layer output
__device__ float g_dinv[N_NODES];
__device__ int   g_cnt[N_NODES];
__device__ int   g_fill[N_NODES];
__device__ int   g_rowptr[N_NODES + 1];
__device__ int   g_csr_src[EMAX];
__device__ float g_csr_w[EMAX];

// ---------------- preprocessing ----------------
__global__ void k_zero(int n) {
    int i = blockIdx.x * blockDim.x + threadIdx.x;
    if (i < n) { g_cnt[i] = 0; g_fill[i] = 0; }
}

__global__ void k_count(const int* __restrict__ dst, int E) {
    int i = blockIdx.x * blockDim.x + threadIdx.x;
    if (i < E) atomicAdd(&g_cnt[dst[i]], 1);
}

__global__ void k_dinv(int n) {
    int i = blockIdx.x * blockDim.x + threadIdx.x;
    if (i < n) g_dinv[i] = rsqrtf((float)(g_cnt[i] + 1));  // +1 self loop
}

// single-block exclusive scan of g_cnt -> g_rowptr
__global__ void k_scan(int n) {
    __shared__ int sh[1024];
    int t = threadIdx.x;
    int chunk = (n + 1023) >> 10;
    int beg = t * chunk;
    int end = min(beg + chunk, n);
    int sum = 0;
    for (int i = beg; i < end; i++) sum += g_cnt[i];
    sh[t] = sum;
    __syncthreads();
    for (int d = 1; d < 1024; d <<= 1) {
        int v = (t >= d) ? sh[t - d] : 0;
        __syncthreads();
        sh[t] += v;
        __syncthreads();
    }
    int off = sh[t] - sum;  // exclusive prefix
    for (int i = beg; i < end; i++) { g_rowptr[i] = off; off += g_cnt[i]; }
    if (t == 1023) g_rowptr[n] = sh[1023];
}

__global__ void k_fill(const int* __restrict__ src, const int* __restrict__ dst, int E) {
    int i = blockIdx.x * blockDim.x + threadIdx.x;
    if (i < E) {
        int d = dst[i];
        int pos = g_rowptr[d] + atomicAdd(&g_fill[d], 1);
        int s = src[i];
        g_csr_src[pos] = s;
        g_csr_w[pos] = g_dinv[s] * g_dinv[d];
    }
}

// ---------------- fp32 GEMM: H[N,128] = X[N,128] @ W[128,128] ----------------
// block = 256 threads, BM=64 rows, k tiled by 32
#define BM 64
#define KT 32
__global__ __launch_bounds__(256) void k_gemm(const float* __restrict__ X,
                                              const float* __restrict__ W,
                                              float* __restrict__ H) {
    __shared__ float4 Ws[KT * F4];        // [k][c4]  32x32 float4 = 16KB
    __shared__ float4 Xs[BM * (KT / 4)];  // [row][k4] 64x8 float4  =  8KB

    int tid = threadIdx.x;
    int tx = tid & 31;          // col group: cols 4*tx..4*tx+3
    int ty = tid >> 5;          // row group: rows ty*8..ty*8+7
    int rbase = blockIdx.x * BM;

    const float4* X4 = (const float4*)X;
    const float4* W4 = (const float4*)W;
    float4* H4 = (float4*)H;

    float4 acc[8];
#pragma unroll
    for (int r = 0; r < 8; r++) acc[r] = make_float4(0.f, 0.f, 0.f, 0.f);

    for (int kc = 0; kc < F / KT; kc++) {
        // load W chunk: KT*F floats = 1024 float4
#pragma unroll
        for (int j = 0; j < 4; j++) {
            int idx = tid + j * 256;
            int k = idx >> 5, c = idx & 31;
            Ws[idx] = W4[(kc * KT + k) * F4 + c];
        }
        // load X chunk: BM*KT floats = 512 float4
#pragma unroll
        for (int j = 0; j < 2; j++) {
            int idx = tid + j * 256;
            int row = idx >> 3, kk = idx & 7;
            int grow = rbase + row;
            Xs[idx] = (grow < N_NODES) ? X4[grow * F4 + kc * 8 + kk]
                                       : make_float4(0.f, 0.f, 0.f, 0.f);
        }
        __syncthreads();

#pragma unroll
        for (int k4 = 0; k4 < KT / 4; k4++) {
            float4 w0 = Ws[(k4 * 4 + 0) * F4 + tx];
            float4 w1 = Ws[(k4 * 4 + 1) * F4 + tx];
            float4 w2 = Ws[(k4 * 4 + 2) * F4 + tx];
            float4 w3 = Ws[(k4 * 4 + 3) * F4 + tx];
#pragma unroll
            for (int r = 0; r < 8; r++) {
                float4 xv = Xs[(ty * 8 + r) * (KT / 4) + k4];
                acc[r].x += xv.x * w0.x; acc[r].y += xv.x * w0.y; acc[r].z += xv.x * w0.z; acc[r].w += xv.x * w0.w;
                acc[r].x += xv.y * w1.x; acc[r].y += xv.y * w1.y; acc[r].z += xv.y * w1.z; acc[r].w += xv.y * w1.w;
                acc[r].x += xv.z * w2.x; acc[r].y += xv.z * w2.y; acc[r].z += xv.z * w2.z; acc[r].w += xv.z * w2.w;
                acc[r].x += xv.w * w3.x; acc[r].y += xv.w * w3.y; acc[r].z += xv.w * w3.z; acc[r].w += xv.w * w3.w;
            }
        }
        __syncthreads();
    }

#pragma unroll
    for (int r = 0; r < 8; r++) {
        int row = rbase + ty * 8 + r;
        if (row < N_NODES) H4[row * F4 + tx] = acc[r];
    }
}

// ---------------- aggregation: warp per node, CSR gather ----------------
__global__ __launch_bounds__(256) void k_agg(const float* __restrict__ H,
                                             const float* __restrict__ b,
                                             float* __restrict__ out,
                                             int do_relu, int dual) {
    int lane = threadIdx.x & 31;
    int node = blockIdx.x * (blockDim.x >> 5) + (threadIdx.x >> 5);
    if (node >= N_NODES) return;

    const float4* H4 = (const float4*)H;
    const float4* b4 = (const float4*)b;
    float4* out4 = (float4*)out;

    float di = g_dinv[node];
    float wself = di * di;
    float4 hv = H4[node * F4 + lane];
    float4 acc = make_float4(wself * hv.x, wself * hv.y, wself * hv.z, wself * hv.w);

    int e0 = g_rowptr[node];
    int e1 = g_rowptr[node + 1];
    for (int e = e0; e < e1; e++) {
        int s = __ldg(&g_csr_src[e]);
        float w = __ldg(&g_csr_w[e]);
        float4 h2 = H4[s * F4 + lane];
        acc.x += w * h2.x; acc.y += w * h2.y; acc.z += w * h2.z; acc.w += w * h2.w;
    }

    float4 bb = b4[lane];
    acc.x += bb.x; acc.y += bb.y; acc.z += bb.z; acc.w += bb.w;
    if (do_relu) {
        acc.x = fmaxf(acc.x, 0.f); acc.y = fmaxf(acc.y, 0.f);
        acc.z = fmaxf(acc.z, 0.f); acc.w = fmaxf(acc.w, 0.f);
    }
    out4[node * F4 + lane] = acc;
    if (dual) out4[N_NODES * F4 + node * F4 + lane] = acc;
}

// ---------------- launch ----------------
extern "C" void kernel_launch(void* const* d_in, const int* in_sizes, int n_in,
                              void* d_out, int out_size) {
    const float* x  = (const float*)d_in[0];
    const int*   ei = (const int*)d_in[1];
    const float* W1 = (const float*)d_in[2];
    const float* b1 = (const float*)d_in[3];
    const float* W2 = (const float*)d_in[4];
    const float* b2 = (const float*)d_in[5];
    const float* W3 = (const float*)d_in[6];
    const float* b3 = (const float*)d_in[7];
    float* out = (float*)d_out;

    int E = in_sizes[1] / 2;
    const int* src = ei;
    const int* dst = ei + E;

    float* g_h_p;    cudaGetSymbolAddress((void**)&g_h_p, g_h);
    float* g_a_p;    cudaGetSymbolAddress((void**)&g_a_p, g_a);

    int nb_n = (N_NODES + 255) / 256;
    int nb_e = (E + 255) / 256;
    int nb_gemm = (N_NODES + BM - 1) / BM;
    int nb_agg = (N_NODES + 7) / 8;

    // preprocessing: degree, dinv, CSR
    k_zero<<<nb_n, 256>>>(N_NODES);
    k_count<<<nb_e, 256>>>(dst, E);
    k_dinv<<<nb_n, 256>>>(N_NODES);
    k_scan<<<1, 1024>>>(N_NODES);
    k_fill<<<nb_e, 256>>>(src, dst, E);

    int dual = (out_size >= 2 * N_NODES * F) ? 1 : 0;

    // layer 1
    k_gemm<<<nb_gemm, 256>>>(x, W1, g_h_p);
    k_agg<<<nb_agg, 256>>>(g_h_p, b1, g_a_p, 1, 0);
    // layer 2
    k_gemm<<<nb_gemm, 256>>>(g_a_p, W2, g_h_p);
    k_agg<<<nb_agg, 256>>>(g_h_p, b2, g_a_p, 1, 0);
    // layer 3
    k_gemm<<<nb_gemm, 256>>>(g_a_p, W3, g_h_p);
    k_agg<<<nb_agg, 256>>>(g_h_p, b3, out, 0, dual);
}

// round 3
// speedup vs baseline: 1.0914x; 1.0914x over previous
#include <cuda_runtime.h>
#include <math.h>

#define N_NODES 50000
#define F 128
#define F4 (F/4)          // 32 float4 per row
#define EMAX 600000

// ---------------- scratch (no allocations allowed) ----------------
__device__ float g_h[N_NODES * F];     // GEMM output (gather table)
__device__ float g_a[N_NODES * F];     // aggregated layer output
__device__ float g_dinv[N_NODES];
__device__ int   g_cnt[N_NODES];
__device__ int   g_fill[N_NODES];
__device__ int   g_rowptr[N_NODES];
__device__ int   g_csr_src[EMAX];
__device__ float g_csr_w[EMAX];
__device__ int   g_total;

// ---------------- preprocessing ----------------
__global__ void k_zero(int n) {
    int i = blockIdx.x * blockDim.x + threadIdx.x;
    if (i < n) { g_cnt[i] = 0; g_fill[i] = 0; }
    if (i == 0) g_total = 0;
}

__global__ void k_count(const int* __restrict__ dst, int E) {
    int i = blockIdx.x * blockDim.x + threadIdx.x;
    if (i < E) atomicAdd(&g_cnt[dst[i]], 1);
}

// one-pass scan: block-local exclusive scan + atomic block base.
// Cross-block ordering of row ranges is irrelevant (each node gets a unique
// contiguous range; k_agg uses rowptr+cnt, never rowptr[i+1]).
__global__ __launch_bounds__(256) void k_scanblk(int n) {
    int i = blockIdx.x * 256 + threadIdx.x;
    int lane = threadIdx.x & 31, wid = threadIdx.x >> 5;
    int v = (i < n) ? g_cnt[i] : 0;
    int incl = v;
#pragma unroll
    for (int d = 1; d < 32; d <<= 1) {
        int t = __shfl_up_sync(0xffffffffu, incl, d);
        if (lane >= d) incl += t;
    }
    __shared__ int wsum[8];
    __shared__ int base_sh;
    if (lane == 31) wsum[wid] = incl;
    __syncthreads();
    if (wid == 0) {
        int ws = (lane < 8) ? wsum[lane] : 0;
        int wincl = ws;
#pragma unroll
        for (int d = 1; d < 8; d <<= 1) {
            int t = __shfl_up_sync(0xffffffffu, wincl, d);
            if (lane >= d) wincl += t;
        }
        if (lane < 8) wsum[lane] = wincl - ws;   // exclusive warp offset
        if (lane == 7) base_sh = atomicAdd(&g_total, wincl);  // block total
    }
    __syncthreads();
    if (i < n) {
        g_rowptr[i] = base_sh + wsum[wid] + incl - v;
        g_dinv[i] = rsqrtf((float)(v + 1));  // +1 self loop
    }
}

__global__ void k_fill(const int* __restrict__ src, const int* __restrict__ dst, int E) {
    int i = blockIdx.x * blockDim.x + threadIdx.x;
    if (i < E) {
        int d = dst[i];
        int pos = g_rowptr[d] + atomicAdd(&g_fill[d], 1);
        int s = src[i];
        g_csr_src[pos] = s;
        g_csr_w[pos] = g_dinv[s] * g_dinv[d];
    }
}

// ---------------- fp32 GEMM with packed f32x2 FMA ----------------
// H[N,128] = X[N,128] @ W[128,128]
// block = 256 threads, BM=64 rows, k tiled by KT=32.
// Accumulators packed over column pairs; W pairs come naturally from the
// float4 smem tile; X is stored to smem pre-duplicated as (x,x) u64 pairs.
#define BM 64
#define KT 32
#define XS_STRIDE 34   // u64 per row (KT + 2 pad: keeps 16B alignment, kills store conflicts)

__device__ __forceinline__ void fma2(unsigned long long& d,
                                     unsigned long long a,
                                     unsigned long long b) {
    asm("fma.rn.f32x2 %0, %1, %2, %0;" : "+l"(d) : "l"(a), "l"(b));
}
__device__ __forceinline__ unsigned long long pack2(float x) {
    unsigned long long p;
    asm("mov.b64 %0, {%1, %1};" : "=l"(p) : "f"(x));
    return p;
}
__device__ __forceinline__ float2 unpack2(unsigned long long v) {
    float lo, hi;
    asm("mov.b64 {%0, %1}, %2;" : "=f"(lo), "=f"(hi) : "l"(v));
    return make_float2(lo, hi);
}

__global__ __launch_bounds__(256) void k_gemm(const float* __restrict__ X,
                                              const float* __restrict__ W,
                                              float* __restrict__ H) {
    __shared__ __align__(16) float4 Ws[KT * F4];                     // [k][c4] 16KB
    __shared__ __align__(16) unsigned long long Xs2[BM * XS_STRIDE]; // dup pairs ~17KB

    int tid = threadIdx.x;
    int tx = tid & 31;          // col group: cols 4*tx..4*tx+3
    int ty = tid >> 5;          // row group: rows ty*8..ty*8+7
    int rbase = blockIdx.x * BM;

    const float4* X4 = (const float4*)X;
    const float4* W4 = (const float4*)W;
    float4* H4 = (float4*)H;

    unsigned long long acc[8][2];
#pragma unroll
    for (int r = 0; r < 8; r++) { acc[r][0] = 0ull; acc[r][1] = 0ull; }

    for (int kc = 0; kc < F / KT; kc++) {
        // load W chunk: KT*F floats = 1024 float4
#pragma unroll
        for (int j = 0; j < 4; j++) {
            int idx = tid + j * 256;
            int k = idx >> 5, c = idx & 31;
            Ws[idx] = W4[(kc * KT + k) * F4 + c];
        }
        // load X chunk: BM*KT floats = 512 float4, store duplicated pairs
#pragma unroll
        for (int j = 0; j < 2; j++) {
            int idx = tid + j * 256;
            int row = idx >> 3, kk = idx & 7;
            int grow = rbase + row;
            float4 xv = (grow < N_NODES) ? X4[grow * F4 + kc * 8 + kk]
                                         : make_float4(0.f, 0.f, 0.f, 0.f);
            unsigned long long* dp = &Xs2[row * XS_STRIDE + kk * 4];
            dp[0] = pack2(xv.x); dp[1] = pack2(xv.y);
            dp[2] = pack2(xv.z); dp[3] = pack2(xv.w);
        }
        __syncthreads();

#pragma unroll
        for (int k4 = 0; k4 < KT / 4; k4++) {
            // W pairs: float4 -> two u64 halves = cols (4tx,4tx+1) and (4tx+2,4tx+3)
            ulonglong2 w0 = *(const ulonglong2*)&Ws[(k4 * 4 + 0) * F4 + tx];
            ulonglong2 w1 = *(const ulonglong2*)&Ws[(k4 * 4 + 1) * F4 + tx];
            ulonglong2 w2 = *(const ulonglong2*)&Ws[(k4 * 4 + 2) * F4 + tx];
            ulonglong2 w3 = *(const ulonglong2*)&Ws[(k4 * 4 + 3) * F4 + tx];
#pragma unroll
            for (int r = 0; r < 8; r++) {
                const ulonglong2* xp =
                    (const ulonglong2*)&Xs2[(ty * 8 + r) * XS_STRIDE + k4 * 4];
                ulonglong2 a01 = xp[0];   // dup(x[k0]), dup(x[k1])  (uniform: broadcast)
                ulonglong2 a23 = xp[1];   // dup(x[k2]), dup(x[k3])
                fma2(acc[r][0], a01.x, w0.x); fma2(acc[r][1], a01.x, w0.y);
                fma2(acc[r][0], a01.y, w1.x); fma2(acc[r][1], a01.y, w1.y);
                fma2(acc[r][0], a23.x, w2.x); fma2(acc[r][1], a23.x, w2.y);
                fma2(acc[r][0], a23.y, w3.x); fma2(acc[r][1], a23.y, w3.y);
            }
        }
        __syncthreads();
    }

#pragma unroll
    for (int r = 0; r < 8; r++) {
        int row = rbase + ty * 8 + r;
        if (row < N_NODES) {
            float2 lo = unpack2(acc[r][0]);
            float2 hi = unpack2(acc[r][1]);
            H4[row * F4 + tx] = make_float4(lo.x, lo.y, hi.x, hi.y);
        }
    }
}

// ---------------- aggregation: warp per node, CSR gather ----------------
__global__ __launch_bounds__(256) void k_agg(const float* __restrict__ H,
                                             const float* __restrict__ b,
                                             float* __restrict__ out,
                                             int do_relu, int dual) {
    int lane = threadIdx.x & 31;
    int node = blockIdx.x * (blockDim.x >> 5) + (threadIdx.x >> 5);
    if (node >= N_NODES) return;

    const float4* H4 = (const float4*)H;
    const float4* b4 = (const float4*)b;
    float4* out4 = (float4*)out;

    float di = g_dinv[node];
    float wself = di * di;
    float4 hv = H4[node * F4 + lane];
    float4 acc = make_float4(wself * hv.x, wself * hv.y, wself * hv.z, wself * hv.w);

    int e0 = g_rowptr[node];
    int e1 = e0 + g_cnt[node];
#pragma unroll 4
    for (int e = e0; e < e1; e++) {
        int s = __ldg(&g_csr_src[e]);
        float w = __ldg(&g_csr_w[e]);
        float4 h2 = H4[s * F4 + lane];
        acc.x += w * h2.x; acc.y += w * h2.y; acc.z += w * h2.z; acc.w += w * h2.w;
    }

    float4 bb = b4[lane];
    acc.x += bb.x; acc.y += bb.y; acc.z += bb.z; acc.w += bb.w;
    if (do_relu) {
        acc.x = fmaxf(acc.x, 0.f); acc.y = fmaxf(acc.y, 0.f);
        acc.z = fmaxf(acc.z, 0.f); acc.w = fmaxf(acc.w, 0.f);
    }
    out4[node * F4 + lane] = acc;
    if (dual) out4[N_NODES * F4 + node * F4 + lane] = acc;
}

// ---------------- launch ----------------
extern "C" void kernel_launch(void* const* d_in, const int* in_sizes, int n_in,
                              void* d_out, int out_size) {
    const float* x  = (const float*)d_in[0];
    const int*   ei = (const int*)d_in[1];
    const float* W1 = (const float*)d_in[2];
    const float* b1 = (const float*)d_in[3];
    const float* W2 = (const float*)d_in[4];
    const float* b2 = (const float*)d_in[5];
    const float* W3 = (const float*)d_in[6];
    const float* b3 = (const float*)d_in[7];
    float* out = (float*)d_out;

    int E = in_sizes[1] / 2;
    const int* src = ei;
    const int* dst = ei + E;

    float* g_h_p;    cudaGetSymbolAddress((void**)&g_h_p, g_h);
    float* g_a_p;    cudaGetSymbolAddress((void**)&g_a_p, g_a);

    int nb_n = (N_NODES + 255) / 256;
    int nb_e = (E + 255) / 256;
    int nb_gemm = (N_NODES + BM - 1) / BM;
    int nb_agg = (N_NODES + 7) / 8;

    // preprocessing: degree, dinv, CSR
    k_zero<<<nb_n, 256>>>(N_NODES);
    k_count<<<nb_e, 256>>>(dst, E);
    k_scanblk<<<nb_n, 256>>>(N_NODES);
    k_fill<<<nb_e, 256>>>(src, dst, E);

    int dual = (out_size >= 2 * N_NODES * F) ? 1 : 0;

    // layer 1
    k_gemm<<<nb_gemm, 256>>>(x, W1, g_h_p);
    k_agg<<<nb_agg, 256>>>(g_h_p, b1, g_a_p, 1, 0);
    // layer 2
    k_gemm<<<nb_gemm, 256>>>(g_a_p, W2, g_h_p);
    k_agg<<<nb_agg, 256>>>(g_h_p, b2, g_a_p, 1, 0);
    // layer 3
    k_gemm<<<nb_gemm, 256>>>(g_a_p, W3, g_h_p);
    k_agg<<<nb_agg, 256>>>(g_h_p, b3, out, 0, dual);
}

// round 6
// speedup vs baseline: 1.5186x; 1.3914x over previous
#include <cuda_runtime.h>
#include <cuda_bf16.h>
#include <cstdint>
#include <math.h>

#define N_NODES 50000
#define F 128
#define F4 (F/4)
#define EMAX 600000
#define NTILES ((N_NODES + 127) / 128)

// ---------------- scratch ----------------
__device__ float g_h[N_NODES * F];
__device__ float g_a[N_NODES * F];
__device__ float g_dinv[N_NODES];
__device__ int   g_cnt[N_NODES];
__device__ int   g_fill[N_NODES];
__device__ int   g_rowptr[N_NODES];
__device__ unsigned long long g_csr[EMAX];   // packed (w<<32 | src)
__device__ int   g_total;
__device__ __nv_bfloat16 g_wt_hi[F * F];     // Wt[n][k] hi
__device__ __nv_bfloat16 g_wt_lo[F * F];     // Wt[n][k] lo

// ---------------- preprocessing ----------------
__global__ void k_zero(int n) {
    int i = blockIdx.x * blockDim.x + threadIdx.x;
    if (i < n) { g_cnt[i] = 0; g_fill[i] = 0; }
    if (i == 0) g_total = 0;
}
__global__ void k_count(const int* __restrict__ dst, int E) {
    int i = blockIdx.x * blockDim.x + threadIdx.x;
    if (i < E) atomicAdd(&g_cnt[dst[i]], 1);
}
__global__ __launch_bounds__(256) void k_scanblk(int n) {
    int i = blockIdx.x * 256 + threadIdx.x;
    int lane = threadIdx.x & 31, wid = threadIdx.x >> 5;
    int v = (i < n) ? g_cnt[i] : 0;
    int incl = v;
#pragma unroll
    for (int d = 1; d < 32; d <<= 1) {
        int t = __shfl_up_sync(0xffffffffu, incl, d);
        if (lane >= d) incl += t;
    }
    __shared__ int wsum[8];
    __shared__ int base_sh;
    if (lane == 31) wsum[wid] = incl;
    __syncthreads();
    if (wid == 0) {
        int ws = (lane < 8) ? wsum[lane] : 0;
        int wincl = ws;
#pragma unroll
        for (int d = 1; d < 8; d <<= 1) {
            int t = __shfl_up_sync(0xffffffffu, wincl, d);
            if (lane >= d) wincl += t;
        }
        if (lane < 8) wsum[lane] = wincl - ws;
        if (lane == 7) base_sh = atomicAdd(&g_total, wincl);
    }
    __syncthreads();
    if (i < n) {
        g_rowptr[i] = base_sh + wsum[wid] + incl - v;
        g_dinv[i] = rsqrtf((float)(v + 1));
    }
}
__global__ void k_fill(const int* __restrict__ src, const int* __restrict__ dst, int E) {
    int i = blockIdx.x * blockDim.x + threadIdx.x;
    if (i < E) {
        int d = dst[i];
        int pos = g_rowptr[d] + atomicAdd(&g_fill[d], 1);
        int s = src[i];
        float w = g_dinv[s] * g_dinv[d];
        g_csr[pos] = ((unsigned long long)__float_as_uint(w) << 32) | (unsigned)s;
    }
}

// W[k][n] -> Wt[n][k] bf16 hi/lo (per layer, tiny)
__global__ void k_wconv(const float* __restrict__ W) {
    int i = blockIdx.x * blockDim.x + threadIdx.x;   // i = n*128 + k
    int n = i >> 7, k = i & 127;
    float w = W[k * F + n];
    __nv_bfloat16 hi = __float2bfloat16_rn(w);
    g_wt_hi[i] = hi;
    g_wt_lo[i] = __float2bfloat16_rn(w - __bfloat162float(hi));
}

// ---------------- HMMA GEMM: H[N,128] = X[N,128] @ W[128,128] ----------------
// bf16 4-split (hh+hl+lh+ll), fp32 accum via mma.m16n8k16.
#define ASTRIDE 272                       // bytes per row (256 + 16 pad): conflict-free ldmatrix
#define SA_HI 0
#define SA_LO (SA_HI + 128 * ASTRIDE)
#define SB_HI (SA_LO + 128 * ASTRIDE)
#define SB_LO (SB_HI + 128 * ASTRIDE)
#define SM_TOTAL (SB_LO + 128 * ASTRIDE) // 139264 B

__device__ __forceinline__ uint32_t smem_u32(const void* p) {
    uint32_t a;
    asm("{ .reg .u64 t; cvta.to.shared.u64 t, %1; cvt.u32.u64 %0, t; }" : "=r"(a) : "l"(p));
    return a;
}
__device__ __forceinline__ uint32_t pack_bf2(float a, float b) {
    unsigned short u0 = __bfloat16_as_ushort(__float2bfloat16_rn(a));
    unsigned short u1 = __bfloat16_as_ushort(__float2bfloat16_rn(b));
    return ((uint32_t)u1 << 16) | u0;
}
__device__ __forceinline__ float bf_res(float x) {
    return x - __bfloat162float(__float2bfloat16_rn(x));
}

#define LDSM4(r0, r1, r2, r3, addr) \
    asm volatile("ldmatrix.sync.aligned.m8n8.x4.shared.b16 {%0,%1,%2,%3}, [%4];" \
        : "=r"(r0), "=r"(r1), "=r"(r2), "=r"(r3) : "r"(addr))

#define MMA(c, a, b0, b1) \
    asm volatile("mma.sync.aligned.m16n8k16.row.col.f32.bf16.bf16.f32 " \
        "{%0,%1,%2,%3},{%4,%5,%6,%7},{%8,%9},{%0,%1,%2,%3};" \
        : "+f"((c)[0]), "+f"((c)[1]), "+f"((c)[2]), "+f"((c)[3]) \
        : "r"((a)[0]), "r"((a)[1]), "r"((a)[2]), "r"((a)[3]), "r"(b0), "r"(b1))

__global__ __launch_bounds__(256, 1) void k_gemm_mma(const float* __restrict__ X,
                                                     float* __restrict__ H) {
    extern __shared__ __align__(16) char smem[];
    uint32_t sbase = smem_u32(smem);
    int tid = threadIdx.x;
    int wid = tid >> 5, lane = tid & 31;
    int rbase = blockIdx.x * 128;

    // --- load A tile (X rows), convert to hi/lo bf16 in padded smem ---
    const float4* X4 = (const float4*)X;
#pragma unroll
    for (int j = 0; j < 16; j++) {
        int idx = j * 256 + tid;
        int row = idx >> 5, c4 = idx & 31;
        int grow = rbase + row;
        float4 xv = (grow < N_NODES) ? X4[grow * 32 + c4] : make_float4(0.f, 0.f, 0.f, 0.f);
        uint32_t off = row * ASTRIDE + c4 * 8;
        *(uint2*)(smem + SA_HI + off) = make_uint2(pack_bf2(xv.x, xv.y), pack_bf2(xv.z, xv.w));
        *(uint2*)(smem + SA_LO + off) = make_uint2(pack_bf2(bf_res(xv.x), bf_res(xv.y)),
                                                   pack_bf2(bf_res(xv.z), bf_res(xv.w)));
    }
    // --- load B (precomputed Wt[n][k] hi/lo) into padded smem, coalesced ---
    const uint4* WH = (const uint4*)g_wt_hi;
    const uint4* WL = (const uint4*)g_wt_lo;
#pragma unroll
    for (int j = 0; j < 8; j++) {
        int i = j * 256 + tid;                 // 2048 uint4 total
        int row = i >> 4, c16 = i & 15;
        uint32_t off = row * ASTRIDE + c16 * 16;
        *(uint4*)(smem + SB_HI + off) = WH[i];
        *(uint4*)(smem + SB_LO + off) = WL[i];
    }
    __syncthreads();

    // --- mainloop ---
    int mrow = (wid & 3) * 32;
    int ncol = (wid >> 2) * 64;
    // ldmatrix lane addressing
    uint32_t aRow = (lane & 15), aK = (lane >> 4) * 16;
    uint32_t bRow = (lane & 7) + ((lane & 16) >> 1), bK = ((lane >> 3) & 1) * 16;

    uint32_t aHi0 = sbase + SA_HI + (mrow + aRow) * ASTRIDE + aK;
    uint32_t aHi1 = aHi0 + 16 * ASTRIDE;
    uint32_t aLo0 = aHi0 + (SA_LO - SA_HI);
    uint32_t aLo1 = aHi1 + (SA_LO - SA_HI);
    uint32_t bHiBase = sbase + SB_HI + (ncol + bRow) * ASTRIDE + bK;
    uint32_t bLoBase = bHiBase + (SB_LO - SB_HI);

    float acc[2][8][4];
#pragma unroll
    for (int t = 0; t < 2; t++)
#pragma unroll
        for (int j = 0; j < 8; j++)
#pragma unroll
            for (int q = 0; q < 4; q++) acc[t][j][q] = 0.f;

#pragma unroll
    for (int ks = 0; ks < 8; ks++) {
        uint32_t koff = ks * 32;
        uint32_t ah[2][4], al[2][4];
        LDSM4(ah[0][0], ah[0][1], ah[0][2], ah[0][3], aHi0 + koff);
        LDSM4(ah[1][0], ah[1][1], ah[1][2], ah[1][3], aHi1 + koff);
        LDSM4(al[0][0], al[0][1], al[0][2], al[0][3], aLo0 + koff);
        LDSM4(al[1][0], al[1][1], al[1][2], al[1][3], aLo1 + koff);
#pragma unroll
        for (int nt = 0; nt < 4; nt++) {
            uint32_t bh0, bh1, bh2, bh3, bl0, bl1, bl2, bl3;
            LDSM4(bh0, bh1, bh2, bh3, bHiBase + nt * 16 * ASTRIDE + koff);
            LDSM4(bl0, bl1, bl2, bl3, bLoBase + nt * 16 * ASTRIDE + koff);
#pragma unroll
            for (int t = 0; t < 2; t++) {
                MMA(acc[t][2 * nt],     ah[t], bh0, bh1);
                MMA(acc[t][2 * nt],     ah[t], bl0, bl1);
                MMA(acc[t][2 * nt],     al[t], bh0, bh1);
                MMA(acc[t][2 * nt],     al[t], bl0, bl1);
                MMA(acc[t][2 * nt + 1], ah[t], bh2, bh3);
                MMA(acc[t][2 * nt + 1], ah[t], bl2, bl3);
                MMA(acc[t][2 * nt + 1], al[t], bh2, bh3);
                MMA(acc[t][2 * nt + 1], al[t], bl2, bl3);
            }
        }
    }

    // --- epilogue: write C fragments to H ---
    int gr = lane >> 2, tc = lane & 3;
#pragma unroll
    for (int t = 0; t < 2; t++) {
        int r0 = rbase + mrow + t * 16 + gr;
        int r1 = r0 + 8;
#pragma unroll
        for (int j = 0; j < 8; j++) {
            int col = ncol + j * 8 + 2 * tc;
            if (r0 < N_NODES)
                *(float2*)&H[r0 * F + col] = make_float2(acc[t][j][0], acc[t][j][1]);
            if (r1 < N_NODES)
                *(float2*)&H[r1 * F + col] = make_float2(acc[t][j][2], acc[t][j][3]);
        }
    }
}

// ---------------- aggregation: warp per node, CSR gather ----------------
__global__ __launch_bounds__(256) void k_agg(const float* __restrict__ H,
                                             const float* __restrict__ b,
                                             float* __restrict__ out,
                                             int do_relu, int dual) {
    int lane = threadIdx.x & 31;
    int node = blockIdx.x * (blockDim.x >> 5) + (threadIdx.x >> 5);
    if (node >= N_NODES) return;

    const float4* H4 = (const float4*)H;
    const float4* b4 = (const float4*)b;
    float4* out4 = (float4*)out;

    float di = g_dinv[node];
    float wself = di * di;
    float4 hv = H4[node * F4 + lane];
    float4 acc = make_float4(wself * hv.x, wself * hv.y, wself * hv.z, wself * hv.w);

    int e0 = g_rowptr[node];
    int e1 = e0 + g_cnt[node];
#pragma unroll 4
    for (int e = e0; e < e1; e++) {
        unsigned long long v = __ldg(&g_csr[e]);
        int s = (int)(unsigned)v;
        float w = __uint_as_float((unsigned)(v >> 32));
        float4 h2 = H4[s * F4 + lane];
        acc.x += w * h2.x; acc.y += w * h2.y; acc.z += w * h2.z; acc.w += w * h2.w;
    }

    float4 bb = b4[lane];
    acc.x += bb.x; acc.y += bb.y; acc.z += bb.z; acc.w += bb.w;
    if (do_relu) {
        acc.x = fmaxf(acc.x, 0.f); acc.y = fmaxf(acc.y, 0.f);
        acc.z = fmaxf(acc.z, 0.f); acc.w = fmaxf(acc.w, 0.f);
    }
    out4[node * F4 + lane] = acc;
    if (dual) out4[N_NODES * F4 + node * F4 + lane] = acc;
}

// ---------------- launch ----------------
extern "C" void kernel_launch(void* const* d_in, const int* in_sizes, int n_in,
                              void* d_out, int out_size) {
    const float* x  = (const float*)d_in[0];
    const int*   ei = (const int*)d_in[1];
    const float* W1 = (const float*)d_in[2];
    const float* b1 = (const float*)d_in[3];
    const float* W2 = (const float*)d_in[4];
    const float* b2 = (const float*)d_in[5];
    const float* W3 = (const float*)d_in[6];
    const float* b3 = (const float*)d_in[7];
    float* out = (float*)d_out;

    int E = in_sizes[1] / 2;
    const int* src = ei;
    const int* dst = ei + E;

    float* g_h_p;    cudaGetSymbolAddress((void**)&g_h_p, g_h);
    float* g_a_p;    cudaGetSymbolAddress((void**)&g_a_p, g_a);

    cudaFuncSetAttribute(k_gemm_mma, cudaFuncAttributeMaxDynamicSharedMemorySize, SM_TOTAL);

    int nb_n = (N_NODES + 255) / 256;
    int nb_e = (E + 255) / 256;
    int nb_agg = (N_NODES + 7) / 8;

    k_zero<<<nb_n, 256>>>(N_NODES);
    k_count<<<nb_e, 256>>>(dst, E);
    k_scanblk<<<nb_n, 256>>>(N_NODES);
    k_fill<<<nb_e, 256>>>(src, dst, E);

    int dual = (out_size >= 2 * N_NODES * F) ? 1 : 0;

    k_wconv<<<64, 256>>>(W1);
    k_gemm_mma<<<NTILES, 256, SM_TOTAL>>>(x, g_h_p);
    k_agg<<<nb_agg, 256>>>(g_h_p, b1, g_a_p, 1, 0);

    k_wconv<<<64, 256>>>(W2);
    k_gemm_mma<<<NTILES, 256, SM_TOTAL>>>(g_a_p, g_h_p);
    k_agg<<<nb_agg, 256>>>(g_h_p, b2, g_a_p, 1, 0);

    k_wconv<<<64, 256>>>(W3);
    k_gemm_mma<<<NTILES, 256, SM_TOTAL>>>(g_a_p, g_h_p);
    k_agg<<<nb_agg, 256>>>(g_h_p, b3, out, 0, dual);
}